// round 14
// baseline (speedup 1.0000x reference)
#include <cuda_runtime.h>
#include <math.h>

#define NPTS 8192
#define GRP  1024
#define NGRP 8
#define KNN_TOT 360
#define MPAIR (NPTS * 20)
#define EPSV 1e-5

typedef unsigned long long u64;
typedef unsigned int u32;

// ---------------- scratch (static device memory; no allocation) ----------------
struct Scratch {
    int    idx[NPTS * KNN_TOT];
    float  A[NPTS * 64];
    float  B[NPTS * 64];
    float  z[NPTS * 64];
    float  x1[NPTS * 64];
    float  x2[NPTS * 64];
    float  x3[NPTS * 64];
    float  x4[NPTS * 64];
    float  t4[NPTS * 128];
    float  t3[NPTS * 128];
    float  t2[NPTS * 64];
    float  t1[NPTS * 64];
    float  b10[128];
    float  gmax[128];
    double sum[13 * 128];
    double sq[13 * 128];
};
__device__ Scratch g_s;

// ---------------- helpers ----------------
__device__ __forceinline__ float lrelu(float v) { return v >= 0.f ? v : 0.2f * v; }

__device__ __forceinline__ void ffma2(u64 &d, u64 a, u64 b) {
    asm("fma.rn.f32x2 %0, %1, %2, %0;" : "+l"(d) : "l"(a), "l"(b));
}
__device__ __forceinline__ u64 pk2(float x, float y) {
    return (u64)__float_as_uint(x) | ((u64)__float_as_uint(y) << 32);
}
__device__ __forceinline__ float f2lo(u64 v) { return __uint_as_float((unsigned)v); }
__device__ __forceinline__ float f2hi(u64 v) { return __uint_as_float((unsigned)(v >> 32)); }

__device__ __forceinline__ u64 umin64(u64 a, u64 b) { return a < b ? a : b; }
__device__ __forceinline__ u64 umax64(u64 a, u64 b) { return a > b ? a : b; }

__device__ __forceinline__ void atomicMaxFloat(float* addr, float val) {
    int* ai = (int*)addr;
    int old = *ai;
    while (__int_as_float(old) < val) {
        int assumed = old;
        old = atomicCAS(ai, assumed, __float_as_int(val));
        if (old == assumed) break;
    }
}

// ---------------- kNN: EXACT u64 keys, 8 elems/thread register/shuffle bitonic ----------------
#define KNN_REGPASS(S)                                                          \
    {                                                                           \
        _Pragma("unroll")                                                       \
        for (int q = 0; q < 8; q++) {                                           \
            if (!(q & (S))) {                                                   \
                bool dirq = (((r * 8 + q) & size) != 0);                        \
                u64 a = v[q], b = v[q | (S)];                                   \
                u64 lo = umin64(a, b), hi = umax64(a, b);                       \
                v[q]       = dirq ? hi : lo;                                    \
                v[q | (S)] = dirq ? lo : hi;                                    \
            }                                                                   \
        }                                                                       \
    }

#define KNN_REGPASS_ASC(S)                                                      \
    {                                                                           \
        _Pragma("unroll")                                                       \
        for (int q = 0; q < 8; q++) {                                           \
            if (!(q & (S))) {                                                   \
                u64 a = v[q], b = v[q | (S)];                                   \
                v[q]       = umin64(a, b);                                      \
                v[q | (S)] = umax64(a, b);                                      \
            }                                                                   \
        }                                                                       \
    }

__global__ void __launch_bounds__(512) knn_kernel(const float* __restrict__ x,
                                                  int* __restrict__ idxo) {
    __shared__ u64 buf[512 * 9];             // 36 KB; coords aliased at start
    float* sc = (float*)buf;
    const int tid = threadIdx.x;
    const int i0 = blockIdx.x * 4;
    const int base = i0 & ~(GRP - 1);
    const int pt = tid >> 7, r = tid & 127;

    for (int t = tid; t < 3072; t += 512) {
        float val = x[base * 3 + t];
        int row = t / 3, col = t - row * 3;
        sc[col * 1024 + row] = val;
    }
    __syncthreads();

    const int li = (i0 & (GRP - 1)) + pt;
    const float qx = sc[li], qy = sc[1024 + li], qz = sc[2048 + li];
    const float sqi = qx * qx + qy * qy + qz * qz;

    u64 v[8];
    #pragma unroll
    for (int q = 0; q < 8; q++) {
        int j = q * 128 + r;
        float ax = sc[j], ay = sc[1024 + j], az = sc[2048 + j];
        float d = sqi + (ax * ax + ay * ay + az * az)
                - 2.f * (qx * ax + qy * ay + qz * az);
        if (j == li) d = INFINITY;
        u32 ub = __float_as_uint(d);
        ub ^= (ub & 0x80000000u) ? 0xFFFFFFFFu : 0x80000000u;
        v[q] = ((u64)ub << 32) | (u32)j;
    }

    #pragma unroll 1
    for (int size = 2; size <= 512; size <<= 1) {
        #pragma unroll 1
        for (int s = size >> 1; s >= 8; s >>= 1) {
            const bool dir = (r & (size >> 3)) != 0;
            const int m = s >> 3;
            const bool keepMin = ((r & m) == 0) != dir;
            if (s <= 128) {
                #pragma unroll
                for (int q = 0; q < 8; q++) {
                    u64 o = __shfl_xor_sync(0xFFFFFFFFu, v[q], m);
                    v[q] = keepMin ? umin64(v[q], o) : umax64(v[q], o);
                }
            } else {
                __syncthreads();
                #pragma unroll
                for (int q = 0; q < 8; q++) buf[tid * 9 + q] = v[q];
                __syncthreads();
                const int ptid = tid ^ m;
                #pragma unroll
                for (int q = 0; q < 8; q++) {
                    u64 o = buf[ptid * 9 + q];
                    v[q] = keepMin ? umin64(v[q], o) : umax64(v[q], o);
                }
            }
        }
        if (size > 4) KNN_REGPASS(4);
        if (size > 2) KNN_REGPASS(2);
        KNN_REGPASS(1);
    }

    // final stage (size = 1024, all ascending), pruned to lower 512 slots
    {
        __syncthreads();
        #pragma unroll
        for (int q = 0; q < 8; q++) buf[tid * 9 + q] = v[q];
        __syncthreads();
        {
            const int m = 64;
            const bool keepMin = ((r & m) == 0);
            const int ptid = tid ^ m;
            #pragma unroll
            for (int q = 0; q < 8; q++) {
                u64 o = buf[ptid * 9 + q];
                v[q] = keepMin ? umin64(v[q], o) : umax64(v[q], o);
            }
        }
        __syncthreads();
        if (r < 64) {
            #pragma unroll
            for (int q = 0; q < 8; q++) buf[tid * 9 + q] = v[q];
        }
        __syncthreads();
        if (r < 64) {
            {
                const int m = 32;
                const bool keepMin = ((r & m) == 0);
                const int ptid = tid ^ m;
                #pragma unroll
                for (int q = 0; q < 8; q++) {
                    u64 o = buf[ptid * 9 + q];
                    v[q] = keepMin ? umin64(v[q], o) : umax64(v[q], o);
                }
            }
            #pragma unroll
            for (int m = 16; m >= 1; m >>= 1) {
                const bool keepMin = ((r & m) == 0);
                #pragma unroll
                for (int q = 0; q < 8; q++) {
                    u64 o = __shfl_xor_sync(0xFFFFFFFFu, v[q], m);
                    v[q] = keepMin ? umin64(v[q], o) : umax64(v[q], o);
                }
            }
            KNN_REGPASS_ASC(4);
            KNN_REGPASS_ASC(2);
            KNN_REGPASS_ASC(1);
        }
    }

    if (r < KNN_TOT / 8) {
        const int i = i0 + pt;
        #pragma unroll
        for (int q = 0; q < 8; q++)
            idxo[i * KNN_TOT + r * 8 + q] = base + (int)(v[q] & 0xFFFFFFFFu);
    }
}

// ---------------- A/B precompute edge 1 (raw x, Cin=3) + stat zeroing ----------------
__global__ void __launch_bounds__(256) ab_kernel(const float* __restrict__ X,
                                                 const float* __restrict__ W,
                                                 float* __restrict__ A, float* __restrict__ B,
                                                 double* __restrict__ zsum,
                                                 double* __restrict__ zsq,
                                                 float* __restrict__ zgmax) {
    __shared__ float a_s[3 * 64];
    __shared__ float d_s[3 * 64];
    __shared__ float xs[16 * 64];
    const int tid = threadIdx.x;
    const int n0 = blockIdx.x * 16;

    if (blockIdx.x < 13 && tid < 128) {
        zsum[blockIdx.x * 128 + tid] = 0.0;
        zsq[blockIdx.x * 128 + tid] = 0.0;
    }
    if (blockIdx.x == 13 && tid < 128) zgmax[tid] = -INFINITY;

    if (tid < 3 * 64) {
        int c = tid >> 6, o = tid & 63;
        float wn = W[o * 6 + c];
        float wc = W[o * 6 + 3 + c];
        a_s[c * 64 + o] = wn;
        d_s[c * 64 + o] = wc - wn;
    }
    for (int e = tid; e < 16 * 3; e += 256) {
        int p = e / 3, c = e - p * 3;
        xs[p * 64 + c] = X[(n0 + p) * 3 + c];
    }
    __syncthreads();

    const int o = tid & 63, pg = tid >> 6;
    float aa[4] = {0.f, 0.f, 0.f, 0.f}, bb[4] = {0.f, 0.f, 0.f, 0.f};
    #pragma unroll
    for (int c = 0; c < 3; c++) {
        float wn = a_s[c * 64 + o], wd = d_s[c * 64 + o];
        #pragma unroll
        for (int q = 0; q < 4; q++) {
            float xv = xs[(pg * 4 + q) * 64 + c];
            aa[q] = fmaf(wn, xv, aa[q]);
            bb[q] = fmaf(wd, xv, bb[q]);
        }
    }
    #pragma unroll
    for (int q = 0; q < 4; q++) {
        int n = n0 + pg * 4 + q;
        A[n * 64 + o] = aa[q];
        B[n * 64 + o] = bb[q];
    }
}

// ---------------- fused: finalize previous edge + A/B for this edge ----------------
__global__ void __launch_bounds__(256) abfuse_kernel(
    const float* __restrict__ z,
    const double* __restrict__ s, const double* __restrict__ q_,
    const float* __restrict__ res,
    float* __restrict__ xout,
    const float* __restrict__ W,
    float* __restrict__ A, float* __restrict__ B) {
    __shared__ float a_s[64 * 64];
    __shared__ float d_s[64 * 64];
    __shared__ float xs[16 * 64];
    __shared__ float mean[64], istd[64];
    const int tid = threadIdx.x;
    const int n0 = blockIdx.x * 16;

    for (int e = tid; e < 64 * 64; e += 256) {
        int c = e >> 6, o = e & 63;
        float wn = W[o * 128 + c];
        float wc = W[o * 128 + 64 + c];
        a_s[c * 64 + o] = wn;
        d_s[c * 64 + o] = wc - wn;
    }
    if (tid < 64) {
        double m = s[tid] / (double)MPAIR;
        double vv = q_[tid] / (double)MPAIR - m * m;
        mean[tid] = (float)m;
        istd[tid] = (float)(1.0 / sqrt(vv + EPSV));
    }
    __syncthreads();

    for (int e = tid; e < 16 * 64; e += 256) {
        int p = e >> 6, c = e & 63;
        int n = n0 + p;
        float val = lrelu((z[n * 64 + c] - mean[c]) * istd[c]);
        if (res) val += res[n * 64 + c];
        xs[e] = val;
        xout[n * 64 + c] = val;
    }
    __syncthreads();

    const int o = tid & 63, pg = tid >> 6;
    float aa[4] = {0.f, 0.f, 0.f, 0.f}, bb[4] = {0.f, 0.f, 0.f, 0.f};
    for (int c = 0; c < 64; c++) {
        float wn = a_s[c * 64 + o], wd = d_s[c * 64 + o];
        #pragma unroll
        for (int q = 0; q < 4; q++) {
            float xv = xs[(pg * 4 + q) * 64 + c];
            aa[q] = fmaf(wn, xv, aa[q]);
            bb[q] = fmaf(wd, xv, bb[q]);
        }
    }
    #pragma unroll
    for (int q = 0; q < 4; q++) {
        int n = n0 + pg * 4 + q;
        A[n * 64 + o] = aa[q];
        B[n * 64 + o] = bb[q];
    }
}

// ---------------- y1 statistics (float4, 16 points/block) ----------------
__global__ void __launch_bounds__(256) stats1_kernel(const float4* __restrict__ A4,
                                                     const float4* __restrict__ B4,
                                                     const int* __restrict__ idx, int stride,
                                                     double* __restrict__ gsum,
                                                     double* __restrict__ gsq) {
    __shared__ int jj[16][20];
    __shared__ float r1[64], r2[64];
    const int tid = threadIdx.x;   // 256
    const int n0 = blockIdx.x * 16;
    if (tid < 64) { r1[tid] = 0.f; r2[tid] = 0.f; }
    for (int e = tid; e < 320; e += 256) {
        int p = e / 20, k = e - p * 20;
        jj[p][k] = idx[(n0 + p) * KNN_TOT + k * stride];
    }
    __syncthreads();
    const int p = tid >> 4, c4 = tid & 15;
    float4 bv = B4[(n0 + p) * 16 + c4];
    float4 s1 = {0.f, 0.f, 0.f, 0.f}, s2 = {0.f, 0.f, 0.f, 0.f};
    #pragma unroll
    for (int k = 0; k < 20; k++) {
        float4 a = A4[jj[p][k] * 16 + c4];
        float hx = a.x + bv.x, hy = a.y + bv.y, hz = a.z + bv.z, hw = a.w + bv.w;
        s1.x += hx; s1.y += hy; s1.z += hz; s1.w += hw;
        s2.x = fmaf(hx, hx, s2.x); s2.y = fmaf(hy, hy, s2.y);
        s2.z = fmaf(hz, hz, s2.z); s2.w = fmaf(hw, hw, s2.w);
    }
    atomicAdd(&r1[c4 * 4 + 0], s1.x); atomicAdd(&r1[c4 * 4 + 1], s1.y);
    atomicAdd(&r1[c4 * 4 + 2], s1.z); atomicAdd(&r1[c4 * 4 + 3], s1.w);
    atomicAdd(&r2[c4 * 4 + 0], s2.x); atomicAdd(&r2[c4 * 4 + 1], s2.y);
    atomicAdd(&r2[c4 * 4 + 2], s2.z); atomicAdd(&r2[c4 * 4 + 3], s2.w);
    __syncthreads();
    if (tid < 64) {
        atomicAdd(&gsum[tid], (double)r1[tid]);
        atomicAdd(&gsq[tid], (double)r2[tid]);
    }
}

// ---------------- conv2 + max + y2 stats: cq-split in time, 85-reg budget ----------------
// Weights staged in smem; each thread reloads 16 u64 per cq-half (loop-variant,
// cannot be hoisted). Live set ~64 regs < 85 cap -> no spills, 3 blocks/SM.
__global__ void __launch_bounds__(256, 3) conv2max_kernel(
    const float4* __restrict__ A4, const float4* __restrict__ B4,
    const int* __restrict__ idx, int stride,
    const double* __restrict__ s1sum, const double* __restrict__ s1sq,
    const float4* __restrict__ Wb4,
    float* __restrict__ z,
    double* __restrict__ osum, double* __restrict__ osq) {
    __shared__ __align__(16) float h[2][20][64];
    __shared__ u64 wsm[16][2][64];          // 16 KB
    __shared__ float mean[64], istd[64];
    __shared__ int jj[16][20];
    __shared__ float red[256];
    const int tid = threadIdx.x;     // 256
    const int n0 = blockIdx.x * 16;
    const int o = tid & 63;
    const int sub = (tid >> 6) & 1;
    const int ptc = tid >> 7;

    for (int e = tid; e < 1024; e += 256) {
        int oo = e & 63, cq = e >> 6;
        float4 w = Wb4[oo * 16 + cq];
        wsm[cq][0][oo] = pk2(w.x, w.y);
        wsm[cq][1][oo] = pk2(w.z, w.w);
    }
    if (tid < 64) {
        double m = s1sum[tid] / (double)MPAIR;
        double v = s1sq[tid] / (double)MPAIR - m * m;
        mean[tid] = (float)m;
        istd[tid] = (float)(1.0 / sqrt(v + EPSV));
    }
    for (int e = tid; e < 320; e += 256) {
        int p = e / 20, k = e - p * 20;
        jj[p][k] = idx[(n0 + p) * KNN_TOT + k * stride];
    }
    __syncthreads();

    float sA = 0.f, sQ = 0.f;
    #pragma unroll 1
    for (int pp = 0; pp < 16; pp += 2) {
        for (int e = tid; e < 640; e += 256) {
            int k2 = e >> 4, cq = e & 15;
            int pt = (k2 >= 20);
            int k = k2 - 20 * pt;
            int n = n0 + pp + pt;
            float4 a = A4[jj[pp + pt][k] * 16 + cq];
            float4 b = B4[n * 16 + cq];
            int c0 = cq * 4;
            float4 r;
            r.x = lrelu((a.x + b.x - mean[c0 + 0]) * istd[c0 + 0]);
            r.y = lrelu((a.y + b.y - mean[c0 + 1]) * istd[c0 + 1]);
            r.z = lrelu((a.z + b.z - mean[c0 + 2]) * istd[c0 + 2]);
            r.w = lrelu((a.w + b.w - mean[c0 + 3]) * istd[c0 + 3]);
            *(float4*)&h[pt][k][c0] = r;
        }
        __syncthreads();

        float ymax = -INFINITY;
        #pragma unroll
        for (int half = 0; half < 2; half++) {
            u64 acc[10];
            #pragma unroll
            for (int q = 0; q < 10; q++) acc[q] = 0ull;
            const int kb = sub * 10 + half * 5;
            #pragma unroll 1
            for (int chalf = 0; chalf < 2; chalf++) {
                u64 w2[16];
                #pragma unroll
                for (int cq = 0; cq < 8; cq++) {
                    w2[cq * 2]     = wsm[chalf * 8 + cq][0][o];
                    w2[cq * 2 + 1] = wsm[chalf * 8 + cq][1][o];
                }
                #pragma unroll
                for (int cq = 0; cq < 8; cq++) {
                    #pragma unroll
                    for (int q = 0; q < 5; q++) {
                        const u64* hv = (const u64*)&h[ptc][kb + q][(chalf * 8 + cq) * 4];
                        ffma2(acc[q * 2],     w2[cq * 2],     hv[0]);
                        ffma2(acc[q * 2 + 1], w2[cq * 2 + 1], hv[1]);
                    }
                }
            }
            #pragma unroll
            for (int q = 0; q < 5; q++) {
                float y = (f2lo(acc[q * 2]) + f2hi(acc[q * 2])) +
                          (f2lo(acc[q * 2 + 1]) + f2hi(acc[q * 2 + 1]));
                sA += y;
                sQ = fmaf(y, y, sQ);
                ymax = fmaxf(ymax, y);
            }
        }
        red[tid] = ymax;
        __syncthreads();
        if (tid < 128) {
            int pt = tid >> 6, oo = tid & 63;
            z[(n0 + pp + pt) * 64 + oo] =
                fmaxf(red[pt * 128 + oo], red[pt * 128 + 64 + oo]);
        }
        __syncthreads();
    }
    red[tid] = sA;
    __syncthreads();
    if (tid < 64)
        atomicAdd(&osum[tid], (double)(red[tid] + red[tid + 64] + red[tid + 128] + red[tid + 192]));
    __syncthreads();
    red[tid] = sQ;
    __syncthreads();
    if (tid < 64)
        atomicAdd(&osq[tid], (double)(red[tid] + red[tid + 64] + red[tid + 128] + red[tid + 192]));
}

// ---------------- g stats + fused edge-4 finalize (256 thr, 2 point-groups) ----------------
__global__ void __launch_bounds__(256) gstat_kernel(
    const float* __restrict__ x1, const float* __restrict__ x2,
    const float* __restrict__ x3,
    const float* __restrict__ z,
    const double* __restrict__ s7, const double* __restrict__ q7,
    float* __restrict__ x4,
    const float* __restrict__ W9,
    double* __restrict__ gsum, double* __restrict__ gsq, float* __restrict__ gmax) {
    extern __shared__ float ws[];               // 128 * 258
    __shared__ __align__(16) float f[8 * 256];
    __shared__ float m4[64], i4[64];
    const int tid = threadIdx.x;  // 256
    for (int e = tid; e < 128 * 256; e += 256) {
        int o = e >> 8, c = e & 255;
        ws[o * 258 + c] = W9[e];
    }
    if (tid < 64) {
        double m = s7[tid] / (double)MPAIR;
        double v = q7[tid] / (double)MPAIR - m * m;
        m4[tid] = (float)m;
        i4[tid] = (float)(1.0 / sqrt(v + EPSV));
    }
    __syncthreads();
    const int o = tid & 127;
    const int half = tid >> 7;
    float ls = 0.f, lq = 0.f, lm = -INFINITY;
    const int n0 = blockIdx.x * 64;
    const u64* wrow = (const u64*)(ws + o * 258);
    for (int it = 0; it < 8; it++) {
        int nb = n0 + it * 8;
        for (int e = tid; e < 2048; e += 256) {
            int p = e >> 8, c = e & 255;
            int n = nb + p, cc = c & 63;
            float val;
            if (c < 64)       val = x1[n * 64 + cc];
            else if (c < 128) val = x2[n * 64 + cc];
            else if (c < 192) val = x3[n * 64 + cc];
            else {
                val = lrelu((z[n * 64 + cc] - m4[cc]) * i4[cc]) + x3[n * 64 + cc];
                x4[n * 64 + cc] = val;
            }
            f[e] = val;
        }
        __syncthreads();
        u64 acc[4] = {0ull, 0ull, 0ull, 0ull};
        const u64* f2 = (const u64*)f;
        const int pb = half * 4;
        #pragma unroll 8
        for (int c2 = 0; c2 < 128; c2++) {
            u64 w = wrow[c2];
            #pragma unroll
            for (int q = 0; q < 4; q++) ffma2(acc[q], w, f2[(pb + q) * 128 + c2]);
        }
        #pragma unroll
        for (int q = 0; q < 4; q++) {
            float y = f2lo(acc[q]) + f2hi(acc[q]);
            ls += y;
            lq = fmaf(y, y, lq);
            lm = fmaxf(lm, y);
        }
        __syncthreads();
    }
    atomicAdd(&gsum[o], (double)ls);
    atomicAdd(&gsq[o], (double)lq);
    atomicMaxFloat(&gmax[o], lm);
}

// ---------------- g finalize + b10 ----------------
__global__ void gfinal_kernel(const double* __restrict__ gsum, const double* __restrict__ gsq,
                              const float* __restrict__ gmax,
                              const float* __restrict__ W10, float* __restrict__ b10) {
    __shared__ float gg[128];
    int tid = threadIdx.x;   // 128
    double m = gsum[tid] / 8192.0;
    double v = gsq[tid] / 8192.0 - m * m;
    float u = (gmax[tid] - (float)m) * (float)(1.0 / sqrt(v + EPSV));
    gg[tid] = lrelu(u);
    __syncthreads();
    float acc = 0.f;
    #pragma unroll 4
    for (int c = 0; c < 128; c++) acc = fmaf(W10[tid * 192 + c], gg[c], acc);
    b10[tid] = acc;
}

// ---------------- generic 1d block: W in smem, f32x2, 32 pts/block ----------------
__global__ void __launch_bounds__(256) mm1d_kernel(
    int C1, int woff1, const double* __restrict__ s1, const double* __restrict__ q1,
    const float* __restrict__ in1,
    int C2, int woff2, const float* __restrict__ in2,
    int O, int rowlen, const float* __restrict__ W, const float* __restrict__ bias,
    float* __restrict__ out,
    double* __restrict__ osum, double* __restrict__ osq) {
    extern __shared__ float ws[];       // O * CP, CP = CT+2 (even)
    __shared__ __align__(16) float f[16 * 192];
    __shared__ float mean[128], istd[128];
    const int tid = threadIdx.x;   // 256
    const int CT = C1 + C2, CP = CT + 2;

    for (int e = tid; e < O * CT; e += 256) {
        int oo = e / CT, cc = e - oo * CT;
        int col = (cc < C1) ? (woff1 + cc) : (woff2 + cc - C1);
        ws[oo * CP + cc] = W[oo * rowlen + col];
    }
    if (s1 && tid < C1) {
        double m = s1[tid] / 8192.0;
        double v = q1[tid] / 8192.0 - m * m;
        mean[tid] = (float)m;
        istd[tid] = (float)(1.0 / sqrt(v + EPSV));
    }
    __syncthreads();

    const int reps = 256 / O;
    const int o = tid & (O - 1);
    const int rep = tid / O;
    const int PG = 4 * reps;
    const int n0 = blockIdx.x * 32;
    const float binit = bias ? bias[o] : 0.f;
    float ls = 0.f, lq = 0.f;

    for (int it = 0; it < 32 / PG; it++) {
        int nb = n0 + it * PG;
        for (int e = tid; e < PG * CT; e += 256) {
            int p = e / CT, c = e - p * CT;
            float v;
            if (c < C1) {
                v = in1[(nb + p) * C1 + c];
                if (s1) v = lrelu((v - mean[c]) * istd[c]);
            } else {
                v = in2[(nb + p) * C2 + (c - C1)];
            }
            f[e] = v;
        }
        __syncthreads();
        u64 acc[4];
        #pragma unroll
        for (int q = 0; q < 4; q++) acc[q] = (u64)__float_as_uint(binit);
        const int pb = rep * 4;
        const float* wr = ws + o * CP;
        for (int c2 = 0; c2 < CT / 2; c2++) {
            u64 w = *(const u64*)(wr + 2 * c2);
            #pragma unroll
            for (int q = 0; q < 4; q++)
                ffma2(acc[q], w, *(const u64*)&f[(pb + q) * CT + 2 * c2]);
        }
        #pragma unroll
        for (int q = 0; q < 4; q++) {
            float y = f2lo(acc[q]) + f2hi(acc[q]);
            out[(nb + pb + q) * O + o] = y;
            ls += y;
            lq = fmaf(y, y, lq);
        }
        __syncthreads();
    }
    atomicAdd(&osum[o], (double)ls);
    atomicAdd(&osq[o], (double)lq);
}

// ---------------- per-group means of normalized t1 + final Wr matmul ----------------
__global__ void gmean_out_kernel(const float* __restrict__ t1,
                                 const double* __restrict__ s, const double* __restrict__ q,
                                 const float* __restrict__ Wr,
                                 float* __restrict__ out) {
    __shared__ float mean[64], istd[64];
    __shared__ float r[256];
    __shared__ float Mo[64];
    int tid = threadIdx.x;   // 256
    int g = blockIdx.x;
    if (tid < 64) {
        double m = s[tid] / 8192.0;
        double v = q[tid] / 8192.0 - m * m;
        mean[tid] = (float)m;
        istd[tid] = (float)(1.0 / sqrt(v + EPSV));
    }
    __syncthreads();
    int c = tid & 63, a = tid >> 6;
    float acc = 0.f;
    for (int nn = a; nn < 1024; nn += 4) {
        int n = g * 1024 + nn;
        acc += lrelu((t1[n * 64 + c] - mean[c]) * istd[c]);
    }
    r[tid] = acc;
    __syncthreads();
    if (tid < 64)
        Mo[tid] = (r[tid] + r[tid + 64] + r[tid + 128] + r[tid + 192]) * (1.f / 1024.f);
    __syncthreads();
    if (tid < 128) {
        float o = 0.f;
        #pragma unroll 4
        for (int cc = 0; cc < 64; cc++) o = fmaf(Wr[tid * 64 + cc], Mo[cc], o);
        out[g * 128 + tid] = o;
    }
}

// ---------------- host ----------------
extern "C" void kernel_launch(void* const* d_in, const int* in_sizes, int n_in,
                              void* d_out, int out_size) {
    const float* x = (const float*)d_in[0];
    int base = 2;
    if (n_in >= 3 && in_sizes[2] == 1) base = 3;
    const float* W[14];
    for (int i = 0; i < 14; i++) W[i] = (const float*)d_in[base + i];

    Scratch* S = nullptr;
    cudaGetSymbolAddress((void**)&S, g_s);
    float* out = (float*)d_out;

    double* SUM = S->sum;
    double* SQ  = S->sq;

    cudaFuncSetAttribute(gstat_kernel, cudaFuncAttributeMaxDynamicSharedMemorySize, 128 * 258 * 4);
    cudaFuncSetAttribute(mm1d_kernel,  cudaFuncAttributeMaxDynamicSharedMemorySize, 128 * 194 * 4);

    const int strides[4] = {1, 2, 6, 18};

    ab_kernel<<<NPTS / 16, 256>>>(x, W[0], S->A, S->B, SUM, SQ, S->gmax);
    knn_kernel<<<NPTS / 4, 512>>>(x, S->idx);
    stats1_kernel<<<NPTS / 16, 256>>>((const float4*)S->A, (const float4*)S->B,
                                      S->idx, strides[0], SUM, SQ);
    conv2max_kernel<<<NPTS / 16, 256>>>((const float4*)S->A, (const float4*)S->B,
                                        S->idx, strides[0], SUM, SQ,
                                        (const float4*)W[1],
                                        S->z, SUM + 128, SQ + 128);

    const float* resi[3] = {nullptr, S->x1, S->x2};
    float*       xout[3] = {S->x1, S->x2, S->x3};
    for (int e = 1; e < 4; e++) {
        int sp = 2 * e - 1;
        int s0 = 2 * e, s1 = 2 * e + 1;
        abfuse_kernel<<<NPTS / 16, 256>>>(S->z, SUM + sp * 128, SQ + sp * 128,
                                          resi[e - 1], xout[e - 1],
                                          W[2 * e], S->A, S->B);
        stats1_kernel<<<NPTS / 16, 256>>>((const float4*)S->A, (const float4*)S->B,
                                          S->idx, strides[e],
                                          SUM + s0 * 128, SQ + s0 * 128);
        conv2max_kernel<<<NPTS / 16, 256>>>((const float4*)S->A, (const float4*)S->B,
                                            S->idx, strides[e],
                                            SUM + s0 * 128, SQ + s0 * 128,
                                            (const float4*)W[2 * e + 1],
                                            S->z, SUM + s1 * 128, SQ + s1 * 128);
    }

    gstat_kernel<<<128, 256, 128 * 258 * 4>>>(S->x1, S->x2, S->x3,
                                              S->z, SUM + 7 * 128, SQ + 7 * 128, S->x4,
                                              W[8],
                                              SUM + 8 * 128, SQ + 8 * 128, S->gmax);
    gfinal_kernel<<<1, 128>>>(SUM + 8 * 128, SQ + 8 * 128, S->gmax, W[9], S->b10);

    mm1d_kernel<<<256, 256, 128 * 66 * 4>>>(
        64, 128, nullptr, nullptr, S->x4,
        0, 0, nullptr,
        128, 192, W[9], S->b10,
        S->t4, SUM + 9 * 128, SQ + 9 * 128);
    mm1d_kernel<<<256, 256, 128 * 194 * 4>>>(
        128, 0, SUM + 9 * 128, SQ + 9 * 128, S->t4,
        64, 128, S->x3,
        128, 192, W[10], nullptr,
        S->t3, SUM + 10 * 128, SQ + 10 * 128);
    mm1d_kernel<<<256, 256, 64 * 194 * 4>>>(
        128, 0, SUM + 10 * 128, SQ + 10 * 128, S->t3,
        64, 128, S->x2,
        64, 192, W[11], nullptr,
        S->t2, SUM + 11 * 128, SQ + 11 * 128);
    mm1d_kernel<<<256, 256, 64 * 130 * 4>>>(
        64, 0, SUM + 11 * 128, SQ + 11 * 128, S->t2,
        64, 64, S->x1,
        64, 128, W[12], nullptr,
        S->t1, SUM + 12 * 128, SQ + 12 * 128);

    gmean_out_kernel<<<NGRP, 256>>>(S->t1, SUM + 12 * 128, SQ + 12 * 128, W[13], out);
}

// round 15
// speedup vs baseline: 1.1058x; 1.1058x over previous
#include <cuda_runtime.h>
#include <math.h>

#define NPTS 8192
#define GRP  1024
#define NGRP 8
#define KNN_TOT 360
#define MPAIR (NPTS * 20)
#define EPSV 1e-5

typedef unsigned long long u64;
typedef unsigned int u32;

// ---------------- scratch (static device memory; no allocation) ----------------
struct Scratch {
    int    idx[NPTS * KNN_TOT];
    float  A[NPTS * 64];
    float  B[NPTS * 64];
    float  z[NPTS * 64];
    float  x1[NPTS * 64];
    float  x2[NPTS * 64];
    float  x3[NPTS * 64];
    float  x4[NPTS * 64];
    float  t4[NPTS * 128];
    float  t3[NPTS * 128];
    float  t2[NPTS * 64];
    float  t1[NPTS * 64];
    float  b10[128];
    float  gmax[128];
    double sum[13 * 128];
    double sq[13 * 128];
};
__device__ Scratch g_s;

// ---------------- helpers ----------------
__device__ __forceinline__ float lrelu(float v) { return v >= 0.f ? v : 0.2f * v; }

__device__ __forceinline__ void ffma2(u64 &d, u64 a, u64 b) {
    asm("fma.rn.f32x2 %0, %1, %2, %0;" : "+l"(d) : "l"(a), "l"(b));
}
__device__ __forceinline__ u64 pk2(float x, float y) {
    return (u64)__float_as_uint(x) | ((u64)__float_as_uint(y) << 32);
}
__device__ __forceinline__ float f2lo(u64 v) { return __uint_as_float((unsigned)v); }
__device__ __forceinline__ float f2hi(u64 v) { return __uint_as_float((unsigned)(v >> 32)); }

__device__ __forceinline__ u64 umin64(u64 a, u64 b) { return a < b ? a : b; }
__device__ __forceinline__ u64 umax64(u64 a, u64 b) { return a > b ? a : b; }

__device__ __forceinline__ void atomicMaxFloat(float* addr, float val) {
    int* ai = (int*)addr;
    int old = *ai;
    while (__int_as_float(old) < val) {
        int assumed = old;
        old = atomicCAS(ai, assumed, __float_as_int(val));
        if (old == assumed) break;
    }
}

// ---------------- kNN: EXACT u64 keys, 8 elems/thread register/shuffle bitonic ----------------
#define KNN_REGPASS(S)                                                          \
    {                                                                           \
        _Pragma("unroll")                                                       \
        for (int q = 0; q < 8; q++) {                                           \
            if (!(q & (S))) {                                                   \
                bool dirq = (((r * 8 + q) & size) != 0);                        \
                u64 a = v[q], b = v[q | (S)];                                   \
                u64 lo = umin64(a, b), hi = umax64(a, b);                       \
                v[q]       = dirq ? hi : lo;                                    \
                v[q | (S)] = dirq ? lo : hi;                                    \
            }                                                                   \
        }                                                                       \
    }

#define KNN_REGPASS_ASC(S)                                                      \
    {                                                                           \
        _Pragma("unroll")                                                       \
        for (int q = 0; q < 8; q++) {                                           \
            if (!(q & (S))) {                                                   \
                u64 a = v[q], b = v[q | (S)];                                   \
                v[q]       = umin64(a, b);                                      \
                v[q | (S)] = umax64(a, b);                                      \
            }                                                                   \
        }                                                                       \
    }

__global__ void __launch_bounds__(512) knn_kernel(const float* __restrict__ x,
                                                  int* __restrict__ idxo) {
    __shared__ u64 buf[512 * 9];
    float* sc = (float*)buf;
    const int tid = threadIdx.x;
    const int i0 = blockIdx.x * 4;
    const int base = i0 & ~(GRP - 1);
    const int pt = tid >> 7, r = tid & 127;

    for (int t = tid; t < 3072; t += 512) {
        float val = x[base * 3 + t];
        int row = t / 3, col = t - row * 3;
        sc[col * 1024 + row] = val;
    }
    __syncthreads();

    const int li = (i0 & (GRP - 1)) + pt;
    const float qx = sc[li], qy = sc[1024 + li], qz = sc[2048 + li];
    const float sqi = qx * qx + qy * qy + qz * qz;

    u64 v[8];
    #pragma unroll
    for (int q = 0; q < 8; q++) {
        int j = q * 128 + r;
        float ax = sc[j], ay = sc[1024 + j], az = sc[2048 + j];
        float d = sqi + (ax * ax + ay * ay + az * az)
                - 2.f * (qx * ax + qy * ay + qz * az);
        if (j == li) d = INFINITY;
        u32 ub = __float_as_uint(d);
        ub ^= (ub & 0x80000000u) ? 0xFFFFFFFFu : 0x80000000u;
        v[q] = ((u64)ub << 32) | (u32)j;
    }

    #pragma unroll 1
    for (int size = 2; size <= 512; size <<= 1) {
        #pragma unroll 1
        for (int s = size >> 1; s >= 8; s >>= 1) {
            const bool dir = (r & (size >> 3)) != 0;
            const int m = s >> 3;
            const bool keepMin = ((r & m) == 0) != dir;
            if (s <= 128) {
                #pragma unroll
                for (int q = 0; q < 8; q++) {
                    u64 o = __shfl_xor_sync(0xFFFFFFFFu, v[q], m);
                    v[q] = keepMin ? umin64(v[q], o) : umax64(v[q], o);
                }
            } else {
                __syncthreads();
                #pragma unroll
                for (int q = 0; q < 8; q++) buf[tid * 9 + q] = v[q];
                __syncthreads();
                const int ptid = tid ^ m;
                #pragma unroll
                for (int q = 0; q < 8; q++) {
                    u64 o = buf[ptid * 9 + q];
                    v[q] = keepMin ? umin64(v[q], o) : umax64(v[q], o);
                }
            }
        }
        if (size > 4) KNN_REGPASS(4);
        if (size > 2) KNN_REGPASS(2);
        KNN_REGPASS(1);
    }

    // final stage (size = 1024, all ascending), pruned to lower 512 slots
    {
        __syncthreads();
        #pragma unroll
        for (int q = 0; q < 8; q++) buf[tid * 9 + q] = v[q];
        __syncthreads();
        {
            const int m = 64;
            const bool keepMin = ((r & m) == 0);
            const int ptid = tid ^ m;
            #pragma unroll
            for (int q = 0; q < 8; q++) {
                u64 o = buf[ptid * 9 + q];
                v[q] = keepMin ? umin64(v[q], o) : umax64(v[q], o);
            }
        }
        __syncthreads();
        if (r < 64) {
            #pragma unroll
            for (int q = 0; q < 8; q++) buf[tid * 9 + q] = v[q];
        }
        __syncthreads();
        if (r < 64) {
            {
                const int m = 32;
                const bool keepMin = ((r & m) == 0);
                const int ptid = tid ^ m;
                #pragma unroll
                for (int q = 0; q < 8; q++) {
                    u64 o = buf[ptid * 9 + q];
                    v[q] = keepMin ? umin64(v[q], o) : umax64(v[q], o);
                }
            }
            #pragma unroll
            for (int m = 16; m >= 1; m >>= 1) {
                const bool keepMin = ((r & m) == 0);
                #pragma unroll
                for (int q = 0; q < 8; q++) {
                    u64 o = __shfl_xor_sync(0xFFFFFFFFu, v[q], m);
                    v[q] = keepMin ? umin64(v[q], o) : umax64(v[q], o);
                }
            }
            KNN_REGPASS_ASC(4);
            KNN_REGPASS_ASC(2);
            KNN_REGPASS_ASC(1);
        }
    }

    if (r < KNN_TOT / 8) {
        const int i = i0 + pt;
        #pragma unroll
        for (int q = 0; q < 8; q++)
            idxo[i * KNN_TOT + r * 8 + q] = base + (int)(v[q] & 0xFFFFFFFFu);
    }
}

// ---------------- A/B precompute edge 1 (raw x, Cin=3) + stat zeroing ----------------
__global__ void __launch_bounds__(256) ab_kernel(const float* __restrict__ X,
                                                 const float* __restrict__ W,
                                                 float* __restrict__ A, float* __restrict__ B,
                                                 double* __restrict__ zsum,
                                                 double* __restrict__ zsq,
                                                 float* __restrict__ zgmax) {
    __shared__ float a_s[3 * 64];
    __shared__ float d_s[3 * 64];
    __shared__ float xs[16 * 64];
    const int tid = threadIdx.x;
    const int n0 = blockIdx.x * 16;

    if (blockIdx.x < 13 && tid < 128) {
        zsum[blockIdx.x * 128 + tid] = 0.0;
        zsq[blockIdx.x * 128 + tid] = 0.0;
    }
    if (blockIdx.x == 13 && tid < 128) zgmax[tid] = -INFINITY;

    if (tid < 3 * 64) {
        int c = tid >> 6, o = tid & 63;
        float wn = W[o * 6 + c];
        float wc = W[o * 6 + 3 + c];
        a_s[c * 64 + o] = wn;
        d_s[c * 64 + o] = wc - wn;
    }
    for (int e = tid; e < 16 * 3; e += 256) {
        int p = e / 3, c = e - p * 3;
        xs[p * 64 + c] = X[(n0 + p) * 3 + c];
    }
    __syncthreads();

    const int o = tid & 63, pg = tid >> 6;
    float aa[4] = {0.f, 0.f, 0.f, 0.f}, bb[4] = {0.f, 0.f, 0.f, 0.f};
    #pragma unroll
    for (int c = 0; c < 3; c++) {
        float wn = a_s[c * 64 + o], wd = d_s[c * 64 + o];
        #pragma unroll
        for (int q = 0; q < 4; q++) {
            float xv = xs[(pg * 4 + q) * 64 + c];
            aa[q] = fmaf(wn, xv, aa[q]);
            bb[q] = fmaf(wd, xv, bb[q]);
        }
    }
    #pragma unroll
    for (int q = 0; q < 4; q++) {
        int n = n0 + pg * 4 + q;
        A[n * 64 + o] = aa[q];
        B[n * 64 + o] = bb[q];
    }
}

// ---------------- fused: finalize previous edge + A/B for this edge ----------------
__global__ void __launch_bounds__(256) abfuse_kernel(
    const float* __restrict__ z,
    const double* __restrict__ s, const double* __restrict__ q_,
    const float* __restrict__ res,
    float* __restrict__ xout,
    const float* __restrict__ W,
    float* __restrict__ A, float* __restrict__ B) {
    __shared__ float a_s[64 * 64];
    __shared__ float d_s[64 * 64];
    __shared__ float xs[16 * 64];
    __shared__ float mean[64], istd[64];
    const int tid = threadIdx.x;
    const int n0 = blockIdx.x * 16;

    for (int e = tid; e < 64 * 64; e += 256) {
        int c = e >> 6, o = e & 63;
        float wn = W[o * 128 + c];
        float wc = W[o * 128 + 64 + c];
        a_s[c * 64 + o] = wn;
        d_s[c * 64 + o] = wc - wn;
    }
    if (tid < 64) {
        double m = s[tid] / (double)MPAIR;
        double vv = q_[tid] / (double)MPAIR - m * m;
        mean[tid] = (float)m;
        istd[tid] = (float)(1.0 / sqrt(vv + EPSV));
    }
    __syncthreads();

    for (int e = tid; e < 16 * 64; e += 256) {
        int p = e >> 6, c = e & 63;
        int n = n0 + p;
        float val = lrelu((z[n * 64 + c] - mean[c]) * istd[c]);
        if (res) val += res[n * 64 + c];
        xs[e] = val;
        xout[n * 64 + c] = val;
    }
    __syncthreads();

    const int o = tid & 63, pg = tid >> 6;
    float aa[4] = {0.f, 0.f, 0.f, 0.f}, bb[4] = {0.f, 0.f, 0.f, 0.f};
    for (int c = 0; c < 64; c++) {
        float wn = a_s[c * 64 + o], wd = d_s[c * 64 + o];
        #pragma unroll
        for (int q = 0; q < 4; q++) {
            float xv = xs[(pg * 4 + q) * 64 + c];
            aa[q] = fmaf(wn, xv, aa[q]);
            bb[q] = fmaf(wd, xv, bb[q]);
        }
    }
    #pragma unroll
    for (int q = 0; q < 4; q++) {
        int n = n0 + pg * 4 + q;
        A[n * 64 + o] = aa[q];
        B[n * 64 + o] = bb[q];
    }
}

// ---------------- y1 statistics (float4, 16 points/block) ----------------
__global__ void __launch_bounds__(256) stats1_kernel(const float4* __restrict__ A4,
                                                     const float4* __restrict__ B4,
                                                     const int* __restrict__ idx, int stride,
                                                     double* __restrict__ gsum,
                                                     double* __restrict__ gsq) {
    __shared__ int jj[16][20];
    __shared__ float r1[64], r2[64];
    const int tid = threadIdx.x;   // 256
    const int n0 = blockIdx.x * 16;
    if (tid < 64) { r1[tid] = 0.f; r2[tid] = 0.f; }
    for (int e = tid; e < 320; e += 256) {
        int p = e / 20, k = e - p * 20;
        jj[p][k] = idx[(n0 + p) * KNN_TOT + k * stride];
    }
    __syncthreads();
    const int p = tid >> 4, c4 = tid & 15;
    float4 bv = B4[(n0 + p) * 16 + c4];
    float4 s1 = {0.f, 0.f, 0.f, 0.f}, s2 = {0.f, 0.f, 0.f, 0.f};
    #pragma unroll
    for (int k = 0; k < 20; k++) {
        float4 a = A4[jj[p][k] * 16 + c4];
        float hx = a.x + bv.x, hy = a.y + bv.y, hz = a.z + bv.z, hw = a.w + bv.w;
        s1.x += hx; s1.y += hy; s1.z += hz; s1.w += hw;
        s2.x = fmaf(hx, hx, s2.x); s2.y = fmaf(hy, hy, s2.y);
        s2.z = fmaf(hz, hz, s2.z); s2.w = fmaf(hw, hw, s2.w);
    }
    atomicAdd(&r1[c4 * 4 + 0], s1.x); atomicAdd(&r1[c4 * 4 + 1], s1.y);
    atomicAdd(&r1[c4 * 4 + 2], s1.z); atomicAdd(&r1[c4 * 4 + 3], s1.w);
    atomicAdd(&r2[c4 * 4 + 0], s2.x); atomicAdd(&r2[c4 * 4 + 1], s2.y);
    atomicAdd(&r2[c4 * 4 + 2], s2.z); atomicAdd(&r2[c4 * 4 + 3], s2.w);
    __syncthreads();
    if (tid < 64) {
        atomicAdd(&gsum[tid], (double)r1[tid]);
        atomicAdd(&gsq[tid], (double)r2[tid]);
    }
}

// ---------------- conv2 + max + y2 stats: r13 compute, 32 pts/block (single wave) ----------------
__global__ void __launch_bounds__(256) conv2max_kernel(
    const float4* __restrict__ A4, const float4* __restrict__ B4,
    const int* __restrict__ idx, int stride,
    const double* __restrict__ s1sum, const double* __restrict__ s1sq,
    const float4* __restrict__ Wb4,
    float* __restrict__ z,
    double* __restrict__ osum, double* __restrict__ osq) {
    __shared__ __align__(16) float h[2][20][64];
    __shared__ float mean[64], istd[64];
    __shared__ int jj[32][20];
    __shared__ float red[256];
    const int tid = threadIdx.x;     // 256
    const int n0 = blockIdx.x * 32;
    const int o = tid & 63;
    const int sub = (tid >> 6) & 1;
    const int ptc = tid >> 7;

    u64 w2[32];
    #pragma unroll
    for (int cq = 0; cq < 16; cq++) {
        float4 w = Wb4[o * 16 + cq];
        w2[cq * 2]     = pk2(w.x, w.y);
        w2[cq * 2 + 1] = pk2(w.z, w.w);
    }
    if (tid < 64) {
        double m = s1sum[tid] / (double)MPAIR;
        double v = s1sq[tid] / (double)MPAIR - m * m;
        mean[tid] = (float)m;
        istd[tid] = (float)(1.0 / sqrt(v + EPSV));
    }
    for (int e = tid; e < 640; e += 256) {
        int p = e / 20, k = e - p * 20;
        jj[p][k] = idx[(n0 + p) * KNN_TOT + k * stride];
    }
    __syncthreads();

    float sA = 0.f, sQ = 0.f;
    #pragma unroll 1
    for (int pp = 0; pp < 32; pp += 2) {
        for (int e = tid; e < 640; e += 256) {
            int k2 = e >> 4, cq = e & 15;
            int pt = (k2 >= 20);
            int k = k2 - 20 * pt;
            int n = n0 + pp + pt;
            float4 a = A4[jj[pp + pt][k] * 16 + cq];
            float4 b = B4[n * 16 + cq];
            int c0 = cq * 4;
            float4 r;
            r.x = lrelu((a.x + b.x - mean[c0 + 0]) * istd[c0 + 0]);
            r.y = lrelu((a.y + b.y - mean[c0 + 1]) * istd[c0 + 1]);
            r.z = lrelu((a.z + b.z - mean[c0 + 2]) * istd[c0 + 2]);
            r.w = lrelu((a.w + b.w - mean[c0 + 3]) * istd[c0 + 3]);
            *(float4*)&h[pt][k][c0] = r;
        }
        __syncthreads();

        float ymax = -INFINITY;
        #pragma unroll
        for (int half = 0; half < 2; half++) {
            u64 acc[10];
            #pragma unroll
            for (int q = 0; q < 10; q++) acc[q] = 0ull;
            const int kb = sub * 10 + half * 5;
            #pragma unroll
            for (int cq = 0; cq < 16; cq++) {
                #pragma unroll
                for (int q = 0; q < 5; q++) {
                    const u64* hv = (const u64*)&h[ptc][kb + q][cq * 4];
                    ffma2(acc[q * 2],     w2[cq * 2],     hv[0]);
                    ffma2(acc[q * 2 + 1], w2[cq * 2 + 1], hv[1]);
                }
            }
            #pragma unroll
            for (int q = 0; q < 5; q++) {
                float y = (f2lo(acc[q * 2]) + f2hi(acc[q * 2])) +
                          (f2lo(acc[q * 2 + 1]) + f2hi(acc[q * 2 + 1]));
                sA += y;
                sQ = fmaf(y, y, sQ);
                ymax = fmaxf(ymax, y);
            }
        }
        red[tid] = ymax;
        __syncthreads();
        if (tid < 128) {
            int pt = tid >> 6, oo = tid & 63;
            z[(n0 + pp + pt) * 64 + oo] =
                fmaxf(red[pt * 128 + oo], red[pt * 128 + 64 + oo]);
        }
        __syncthreads();
    }
    red[tid] = sA;
    __syncthreads();
    if (tid < 64)
        atomicAdd(&osum[tid], (double)(red[tid] + red[tid + 64] + red[tid + 128] + red[tid + 192]));
    __syncthreads();
    red[tid] = sQ;
    __syncthreads();
    if (tid < 64)
        atomicAdd(&osq[tid], (double)(red[tid] + red[tid + 64] + red[tid + 128] + red[tid + 192]));
}

// ---------------- g stats + fused edge-4 finalize (256 thr, 2 point-groups) ----------------
__global__ void __launch_bounds__(256) gstat_kernel(
    const float* __restrict__ x1, const float* __restrict__ x2,
    const float* __restrict__ x3,
    const float* __restrict__ z,
    const double* __restrict__ s7, const double* __restrict__ q7,
    float* __restrict__ x4,
    const float* __restrict__ W9,
    double* __restrict__ gsum, double* __restrict__ gsq, float* __restrict__ gmax) {
    extern __shared__ float ws[];               // 128 * 258
    __shared__ __align__(16) float f[8 * 256];
    __shared__ float m4[64], i4[64];
    const int tid = threadIdx.x;  // 256
    for (int e = tid; e < 128 * 256; e += 256) {
        int o = e >> 8, c = e & 255;
        ws[o * 258 + c] = W9[e];
    }
    if (tid < 64) {
        double m = s7[tid] / (double)MPAIR;
        double v = q7[tid] / (double)MPAIR - m * m;
        m4[tid] = (float)m;
        i4[tid] = (float)(1.0 / sqrt(v + EPSV));
    }
    __syncthreads();
    const int o = tid & 127;
    const int half = tid >> 7;
    float ls = 0.f, lq = 0.f, lm = -INFINITY;
    const int n0 = blockIdx.x * 64;
    const u64* wrow = (const u64*)(ws + o * 258);
    for (int it = 0; it < 8; it++) {
        int nb = n0 + it * 8;
        for (int e = tid; e < 2048; e += 256) {
            int p = e >> 8, c = e & 255;
            int n = nb + p, cc = c & 63;
            float val;
            if (c < 64)       val = x1[n * 64 + cc];
            else if (c < 128) val = x2[n * 64 + cc];
            else if (c < 192) val = x3[n * 64 + cc];
            else {
                val = lrelu((z[n * 64 + cc] - m4[cc]) * i4[cc]) + x3[n * 64 + cc];
                x4[n * 64 + cc] = val;
            }
            f[e] = val;
        }
        __syncthreads();
        u64 acc[4] = {0ull, 0ull, 0ull, 0ull};
        const u64* f2 = (const u64*)f;
        const int pb = half * 4;
        #pragma unroll 8
        for (int c2 = 0; c2 < 128; c2++) {
            u64 w = wrow[c2];
            #pragma unroll
            for (int q = 0; q < 4; q++) ffma2(acc[q], w, f2[(pb + q) * 128 + c2]);
        }
        #pragma unroll
        for (int q = 0; q < 4; q++) {
            float y = f2lo(acc[q]) + f2hi(acc[q]);
            ls += y;
            lq = fmaf(y, y, lq);
            lm = fmaxf(lm, y);
        }
        __syncthreads();
    }
    atomicAdd(&gsum[o], (double)ls);
    atomicAdd(&gsq[o], (double)lq);
    atomicMaxFloat(&gmax[o], lm);
}

// ---------------- g finalize + b10 ----------------
__global__ void gfinal_kernel(const double* __restrict__ gsum, const double* __restrict__ gsq,
                              const float* __restrict__ gmax,
                              const float* __restrict__ W10, float* __restrict__ b10) {
    __shared__ float gg[128];
    int tid = threadIdx.x;   // 128
    double m = gsum[tid] / 8192.0;
    double v = gsq[tid] / 8192.0 - m * m;
    float u = (gmax[tid] - (float)m) * (float)(1.0 / sqrt(v + EPSV));
    gg[tid] = lrelu(u);
    __syncthreads();
    float acc = 0.f;
    #pragma unroll 4
    for (int c = 0; c < 128; c++) acc = fmaf(W10[tid * 192 + c], gg[c], acc);
    b10[tid] = acc;
}

// ---------------- generic 1d block: W in smem, f32x2, 32 pts/block ----------------
__global__ void __launch_bounds__(256) mm1d_kernel(
    int C1, int woff1, const double* __restrict__ s1, const double* __restrict__ q1,
    const float* __restrict__ in1,
    int C2, int woff2, const float* __restrict__ in2,
    int O, int rowlen, const float* __restrict__ W, const float* __restrict__ bias,
    float* __restrict__ out,
    double* __restrict__ osum, double* __restrict__ osq) {
    extern __shared__ float ws[];       // O * CP, CP = CT+2 (even)
    __shared__ __align__(16) float f[16 * 192];
    __shared__ float mean[128], istd[128];
    const int tid = threadIdx.x;   // 256
    const int CT = C1 + C2, CP = CT + 2;

    for (int e = tid; e < O * CT; e += 256) {
        int oo = e / CT, cc = e - oo * CT;
        int col = (cc < C1) ? (woff1 + cc) : (woff2 + cc - C1);
        ws[oo * CP + cc] = W[oo * rowlen + col];
    }
    if (s1 && tid < C1) {
        double m = s1[tid] / 8192.0;
        double v = q1[tid] / 8192.0 - m * m;
        mean[tid] = (float)m;
        istd[tid] = (float)(1.0 / sqrt(v + EPSV));
    }
    __syncthreads();

    const int reps = 256 / O;
    const int o = tid & (O - 1);
    const int rep = tid / O;
    const int PG = 4 * reps;
    const int n0 = blockIdx.x * 32;
    const float binit = bias ? bias[o] : 0.f;
    float ls = 0.f, lq = 0.f;

    for (int it = 0; it < 32 / PG; it++) {
        int nb = n0 + it * PG;
        for (int e = tid; e < PG * CT; e += 256) {
            int p = e / CT, c = e - p * CT;
            float v;
            if (c < C1) {
                v = in1[(nb + p) * C1 + c];
                if (s1) v = lrelu((v - mean[c]) * istd[c]);
            } else {
                v = in2[(nb + p) * C2 + (c - C1)];
            }
            f[e] = v;
        }
        __syncthreads();
        u64 acc[4];
        #pragma unroll
        for (int q = 0; q < 4; q++) acc[q] = (u64)__float_as_uint(binit);
        const int pb = rep * 4;
        const float* wr = ws + o * CP;
        for (int c2 = 0; c2 < CT / 2; c2++) {
            u64 w = *(const u64*)(wr + 2 * c2);
            #pragma unroll
            for (int q = 0; q < 4; q++)
                ffma2(acc[q], w, *(const u64*)&f[(pb + q) * CT + 2 * c2]);
        }
        #pragma unroll
        for (int q = 0; q < 4; q++) {
            float y = f2lo(acc[q]) + f2hi(acc[q]);
            out[(nb + pb + q) * O + o] = y;
            ls += y;
            lq = fmaf(y, y, lq);
        }
        __syncthreads();
    }
    atomicAdd(&osum[o], (double)ls);
    atomicAdd(&osq[o], (double)lq);
}

// ---------------- per-group means of normalized t1 + final Wr matmul ----------------
__global__ void gmean_out_kernel(const float* __restrict__ t1,
                                 const double* __restrict__ s, const double* __restrict__ q,
                                 const float* __restrict__ Wr,
                                 float* __restrict__ out) {
    __shared__ float mean[64], istd[64];
    __shared__ float r[256];
    __shared__ float Mo[64];
    int tid = threadIdx.x;   // 256
    int g = blockIdx.x;
    if (tid < 64) {
        double m = s[tid] / 8192.0;
        double v = q[tid] / 8192.0 - m * m;
        mean[tid] = (float)m;
        istd[tid] = (float)(1.0 / sqrt(v + EPSV));
    }
    __syncthreads();
    int c = tid & 63, a = tid >> 6;
    float acc = 0.f;
    for (int nn = a; nn < 1024; nn += 4) {
        int n = g * 1024 + nn;
        acc += lrelu((t1[n * 64 + c] - mean[c]) * istd[c]);
    }
    r[tid] = acc;
    __syncthreads();
    if (tid < 64)
        Mo[tid] = (r[tid] + r[tid + 64] + r[tid + 128] + r[tid + 192]) * (1.f / 1024.f);
    __syncthreads();
    if (tid < 128) {
        float o = 0.f;
        #pragma unroll 4
        for (int cc = 0; cc < 64; cc++) o = fmaf(Wr[tid * 64 + cc], Mo[cc], o);
        out[g * 128 + tid] = o;
    }
}

// ---------------- host ----------------
extern "C" void kernel_launch(void* const* d_in, const int* in_sizes, int n_in,
                              void* d_out, int out_size) {
    const float* x = (const float*)d_in[0];
    int base = 2;
    if (n_in >= 3 && in_sizes[2] == 1) base = 3;
    const float* W[14];
    for (int i = 0; i < 14; i++) W[i] = (const float*)d_in[base + i];

    Scratch* S = nullptr;
    cudaGetSymbolAddress((void**)&S, g_s);
    float* out = (float*)d_out;

    double* SUM = S->sum;
    double* SQ  = S->sq;

    cudaFuncSetAttribute(gstat_kernel, cudaFuncAttributeMaxDynamicSharedMemorySize, 128 * 258 * 4);
    cudaFuncSetAttribute(mm1d_kernel,  cudaFuncAttributeMaxDynamicSharedMemorySize, 128 * 194 * 4);

    const int strides[4] = {1, 2, 6, 18};

    ab_kernel<<<NPTS / 16, 256>>>(x, W[0], S->A, S->B, SUM, SQ, S->gmax);
    knn_kernel<<<NPTS / 4, 512>>>(x, S->idx);
    stats1_kernel<<<NPTS / 16, 256>>>((const float4*)S->A, (const float4*)S->B,
                                      S->idx, strides[0], SUM, SQ);
    conv2max_kernel<<<NPTS / 32, 256>>>((const float4*)S->A, (const float4*)S->B,
                                        S->idx, strides[0], SUM, SQ,
                                        (const float4*)W[1],
                                        S->z, SUM + 128, SQ + 128);

    const float* resi[3] = {nullptr, S->x1, S->x2};
    float*       xout[3] = {S->x1, S->x2, S->x3};
    for (int e = 1; e < 4; e++) {
        int sp = 2 * e - 1;
        int s0 = 2 * e, s1 = 2 * e + 1;
        abfuse_kernel<<<NPTS / 16, 256>>>(S->z, SUM + sp * 128, SQ + sp * 128,
                                          resi[e - 1], xout[e - 1],
                                          W[2 * e], S->A, S->B);
        stats1_kernel<<<NPTS / 16, 256>>>((const float4*)S->A, (const float4*)S->B,
                                          S->idx, strides[e],
                                          SUM + s0 * 128, SQ + s0 * 128);
        conv2max_kernel<<<NPTS / 32, 256>>>((const float4*)S->A, (const float4*)S->B,
                                            S->idx, strides[e],
                                            SUM + s0 * 128, SQ + s0 * 128,
                                            (const float4*)W[2 * e + 1],
                                            S->z, SUM + s1 * 128, SQ + s1 * 128);
    }

    gstat_kernel<<<128, 256, 128 * 258 * 4>>>(S->x1, S->x2, S->x3,
                                              S->z, SUM + 7 * 128, SQ + 7 * 128, S->x4,
                                              W[8],
                                              SUM + 8 * 128, SQ + 8 * 128, S->gmax);
    gfinal_kernel<<<1, 128>>>(SUM + 8 * 128, SQ + 8 * 128, S->gmax, W[9], S->b10);

    mm1d_kernel<<<256, 256, 128 * 66 * 4>>>(
        64, 128, nullptr, nullptr, S->x4,
        0, 0, nullptr,
        128, 192, W[9], S->b10,
        S->t4, SUM + 9 * 128, SQ + 9 * 128);
    mm1d_kernel<<<256, 256, 128 * 194 * 4>>>(
        128, 0, SUM + 9 * 128, SQ + 9 * 128, S->t4,
        64, 128, S->x3,
        128, 192, W[10], nullptr,
        S->t3, SUM + 10 * 128, SQ + 10 * 128);
    mm1d_kernel<<<256, 256, 64 * 194 * 4>>>(
        128, 0, SUM + 10 * 128, SQ + 10 * 128, S->t3,
        64, 128, S->x2,
        64, 192, W[11], nullptr,
        S->t2, SUM + 11 * 128, SQ + 11 * 128);
    mm1d_kernel<<<256, 256, 64 * 130 * 4>>>(
        64, 0, SUM + 11 * 128, SQ + 11 * 128, S->t2,
        64, 64, S->x1,
        64, 128, W[12], nullptr,
        S->t1, SUM + 12 * 128, SQ + 12 * 128);

    gmean_out_kernel<<<NGRP, 256>>>(S->t1, SUM + 12 * 128, SQ + 12 * 128, W[13], out);
}